// round 2
// baseline (speedup 1.0000x reference)
#include <cuda_runtime.h>

// Problem constants
#define Bdim   4
#define Tdim   4
#define Cdim   32
#define Ndim   16384
#define Fdim   64
#define Kdim   9
#define PADl   4
#define TILE_N 128
#define CK     (Cdim * Kdim)   // 288

// Pre-transposed weights: [t][ck][f], ck = c*K + k (matches einsum 'tfck' flatten)
__device__ float g_wT[Tdim * CK * Fdim];   // 73728 floats = 288 KB

__global__ void transpose_w_kernel(const float* __restrict__ w) {
    int idx = blockIdx.x * blockDim.x + threadIdx.x;
    if (idx >= Tdim * Fdim * CK) return;
    int t  = idx / (Fdim * CK);
    int r  = idx - t * (Fdim * CK);
    int f  = r / CK;
    int ck = r - f * CK;
    g_wT[(t * CK + ck) * Fdim + f] = w[idx];
}

__global__ __launch_bounds__(256)
void sepconv_kernel(const float* __restrict__ x,
                    const float* __restrict__ coords,
                    const unsigned* __restrict__ sigma_p,
                    float* __restrict__ out)
{
    __shared__ float xs[Cdim][TILE_N + 8];   // x tile with halo     (17408 B)
    __shared__ float cs[3][TILE_N + 8];      // coords tile w/ halo  ( 1632 B)
    __shared__ float ws[Kdim][TILE_N];       // distance weights     ( 4608 B)
    __shared__ float wsh[32][Fdim];          // weight chunk [j][f]  ( 8192 B)
    __shared__ float bs[32][TILE_N];         // Bmat chunk  [j][n]   (16384 B)
    // total 48224 B static shared

    const int tid = threadIdx.x;
    const int bt  = blockIdx.y;          // b*T + t
    const int t   = bt & (Tdim - 1);
    const int n0  = blockIdx.x * TILE_N;

    // sigma: dataset passes python int 2 -> likely int32; tolerate float too.
    unsigned sb = *sigma_p;
    float sigma = (sb < 0x01000000u) ? (float)(int)sb : __uint_as_float(sb);
    float inv_sigma = 1.0f / sigma;

    // ---- stage x tile (with halo, zero-padded) ----
    const float* xb = x + (size_t)bt * Cdim * Ndim;
    for (int idx = tid; idx < Cdim * (TILE_N + 8); idx += 256) {
        int c = idx / (TILE_N + 8);
        int i = idx - c * (TILE_N + 8);
        int m = n0 + i - PADl;
        xs[c][i] = (m >= 0 && m < Ndim) ? xb[c * Ndim + m] : 0.0f;
    }
    // ---- stage coords tile ----
    const float* cb = coords + (size_t)bt * 3 * Ndim;
    for (int idx = tid; idx < 3 * (TILE_N + 8); idx += 256) {
        int d = idx / (TILE_N + 8);
        int i = idx - d * (TILE_N + 8);
        int m = n0 + i - PADl;
        cs[d][i] = (m >= 0 && m < Ndim) ? cb[d * Ndim + m] : 0.0f;
    }
    __syncthreads();

    // ---- distance weights ws[k][n] ----
    for (int idx = tid; idx < Kdim * TILE_N; idx += 256) {
        int k = idx >> 7;          // TILE_N = 128
        int n = idx & 127;
        float dx = cs[0][n + k] - cs[0][n + PADl];
        float dy = cs[1][n + k] - cs[1][n + PADl];
        float dz = cs[2][n + k] - cs[2][n + PADl];
        float d2 = dx * dx + dy * dy + dz * dz;
        float w  = 1.0f - sqrtf(d2) * inv_sigma;
        ws[k][n] = fmaxf(w, 0.0f);
    }
    __syncthreads();

    // ---- register-tiled GEMM: [64 f] x [288 ck] x [128 n] ----
    const int fi = tid >> 4;         // 0..15
    const int ni = tid & 15;         // 0..15
    const int f0 = fi * 4;
    const int nl = ni * 8;

    float acc[4][8];
    #pragma unroll
    for (int a = 0; a < 4; a++)
        #pragma unroll
        for (int b = 0; b < 8; b++) acc[a][b] = 0.0f;

    const float* wtb = g_wT + (size_t)t * CK * Fdim;

    for (int ch = 0; ch < 9; ch++) {
        // fill weight chunk wsh[j][f]  (coalesced gmem, conflict-free STS)
        #pragma unroll
        for (int it = 0; it < 8; it++) {
            int idx = it * 256 + tid;          // j = idx>>6, f = idx&63 contiguous
            wsh[idx >> 6][idx & 63] = wtb[ch * 32 * Fdim + idx];
        }
        // build Bmat chunk bs[j][n] = x[c][n+k] * ws[k][n]
        #pragma unroll
        for (int it = 0; it < 16; it++) {
            int idx = it * 256 + tid;
            int j = idx >> 7, n = idx & 127;
            int ck = ch * 32 + j;
            int c  = ck / 9;
            int k  = ck - c * 9;
            bs[j][n] = xs[c][n + k] * ws[k][n];
        }
        __syncthreads();

        #pragma unroll 8
        for (int j = 0; j < 32; j++) {
            float4 a  = *(const float4*)&wsh[j][f0];
            float4 b0 = *(const float4*)&bs[j][nl];
            float4 b1 = *(const float4*)&bs[j][nl + 4];
            float av[4] = {a.x, a.y, a.z, a.w};
            float bv[8] = {b0.x, b0.y, b0.z, b0.w, b1.x, b1.y, b1.z, b1.w};
            #pragma unroll
            for (int ff = 0; ff < 4; ff++)
                #pragma unroll
                for (int nn = 0; nn < 8; nn++)
                    acc[ff][nn] = fmaf(av[ff], bv[nn], acc[ff][nn]);
        }
        __syncthreads();
    }

    // ---- epilogue: vectorized stores ----
    float* ob = out + (size_t)bt * Fdim * Ndim;
    #pragma unroll
    for (int ff = 0; ff < 4; ff++) {
        float* p = ob + (size_t)(f0 + ff) * Ndim + n0 + nl;
        float4 o0 = make_float4(acc[ff][0], acc[ff][1], acc[ff][2], acc[ff][3]);
        float4 o1 = make_float4(acc[ff][4], acc[ff][5], acc[ff][6], acc[ff][7]);
        *(float4*)p       = o0;
        *(float4*)(p + 4) = o1;
    }
}

extern "C" void kernel_launch(void* const* d_in, const int* in_sizes, int n_in,
                              void* d_out, int out_size)
{
    const float*    x      = (const float*)d_in[0];
    const float*    coords = (const float*)d_in[1];
    const float*    w      = (const float*)d_in[2];
    const unsigned* sigma  = (const unsigned*)d_in[3];
    float*          out    = (float*)d_out;

    transpose_w_kernel<<<(Tdim * Fdim * CK + 255) / 256, 256>>>(w);

    dim3 grid(Ndim / TILE_N, Bdim * Tdim);
    sepconv_kernel<<<grid, 256>>>(x, coords, sigma, out);
}